// round 13
// baseline (speedup 1.0000x reference)
#include <cuda_runtime.h>
#include <cstdint>
#include <cstddef>

#define NJ 24
#define FPS 32                              // frames per slab (= lanes per warp)
#define PA_BYTES (FPS * 576)                // 18432
#define OA_BYTES (FPS * 288)                // 9216
#define SLAB_BYTES (2 * PA_BYTES + 2 * OA_BYTES)   // 55296
#define OFF_PB  (PA_BYTES)
#define OFF_OA  (2 * PA_BYTES)
#define OFF_OB  (2 * PA_BYTES + OA_BYTES)
#define NWARPS 4
#define DYN_SMEM (NWARPS * SLAB_BYTES)      // 221184 B

typedef unsigned long long u64;

__device__ float g_partials[16384];
__device__ unsigned int g_count = 0;

// ---- packed f32x2 primitives (FFMA2 path; PTX-only per SASS_QUICKREF) ----
__device__ __forceinline__ u64 pk(float lo, float hi) {
    u64 r; asm("mov.b64 %0,{%1,%2};" : "=l"(r) : "f"(lo), "f"(hi)); return r;
}
__device__ __forceinline__ void upk(u64 a, float& lo, float& hi) {
    asm("mov.b64 {%0,%1},%2;" : "=f"(lo), "=f"(hi) : "l"(a));
}
__device__ __forceinline__ u64 f2mul(u64 a, u64 b) {
    u64 r; asm("mul.rn.f32x2 %0,%1,%2;" : "=l"(r) : "l"(a), "l"(b)); return r;
}
__device__ __forceinline__ u64 f2fma(u64 a, u64 b, u64 c) {
    u64 r; asm("fma.rn.f32x2 %0,%1,%2,%3;" : "=l"(r) : "l"(a), "l"(b), "l"(c)); return r;
}

// Packed fast inverse sqrt: per-half integer seed (ALU pipe) + 2 packed Newton.
__device__ __forceinline__ u64 rsq2(u64 x, u64 C15, u64 CM05) {
    unsigned lo, hi;
    asm("mov.b64 {%0,%1},%2;" : "=r"(lo), "=r"(hi) : "l"(x));
    lo = 0x5f3759dfu - (lo >> 1);
    hi = 0x5f3759dfu - (hi >> 1);
    u64 y; asm("mov.b64 %0,{%1,%2};" : "=l"(y) : "r"(lo), "r"(hi));
    const u64 nhx = f2mul(x, CM05);          // -x/2
    u64 t = f2mul(y, y); t = f2fma(nhx, t, C15); y = f2mul(y, t);
    t = f2mul(y, y);     t = f2fma(nhx, t, C15); y = f2mul(y, t);
    return y;
}

__device__ __forceinline__ void bulk_g2s(uint32_t dst, const void* src,
                                         uint32_t bytes, uint32_t mbar) {
    asm volatile(
        "cp.async.bulk.shared::cta.global.mbarrier::complete_tx::bytes [%0], [%1], %2, [%3];"
        :: "r"(dst), "l"(src), "r"(bytes), "r"(mbar) : "memory");
}
__device__ __forceinline__ void mbar_init(uint32_t mbar, uint32_t count) {
    asm volatile("mbarrier.init.shared.b64 [%0], %1;" :: "r"(mbar), "r"(count) : "memory");
}
__device__ __forceinline__ void mbar_arrive_expect_tx(uint32_t mbar, uint32_t tx) {
    asm volatile("mbarrier.arrive.expect_tx.shared.b64 _, [%0], %1;"
                 :: "r"(mbar), "r"(tx) : "memory");
}
__device__ __forceinline__ void mbar_wait(uint32_t mbar, uint32_t parity) {
    asm volatile(
        "{\n\t"
        ".reg .pred P;\n\t"
        "WL_%=:\n\t"
        "mbarrier.try_wait.parity.acquire.cta.shared::cta.b64 P, [%0], %1, 0x989680;\n\t"
        "@P bra.uni WD_%=;\n\t"
        "bra.uni WL_%=;\n\t"
        "WD_%=:\n\t"
        "}"
        :: "r"(mbar), "r"(parity) : "memory");
}

// Persistent kernel: grid = #SMs, 128 threads = 4 warps per block. Each warp
// is an independent group streaming 32-frame slabs through its private 54KB
// buffer (4 contiguous-region bulk copies/slab). Each THREAD runs ONE packed
// FK per frame: pose A in lo halves, pose B in hi halves of f32x2 values.
__global__ void __launch_bounds__(128, 1)
ee_loss_kernel(const float* __restrict__ poseA, const float* __restrict__ poseB,
               const float* __restrict__ offA,  const float* __restrict__ offB,
               const float* __restrict__ tA,    const float* __restrict__ tB,
               float* __restrict__ out,
               int F, float inv_count)
{
    constexpr int PARENTS[NJ] = {-1,0,0,0,1,2,3,4,5,6,7,8,9,9,9,12,13,14,16,17,18,19,20,21};
    constexpr bool IS_EE[NJ] = {false,false,false,false,false,false,false,false,false,false,
                                true, true, false,false,false,true, false,false,false,false,
                                false,false,true, true};
    constexpr int EE_SLOT[NJ] = {-1,-1,-1,-1,-1,-1,-1,-1,-1,-1,
                                  0, 1,-1,-1,-1, 2,-1,-1,-1,-1,
                                 -1,-1, 3, 4};
    constexpr int END_SITES[5] = {10,11,15,22,23};

    extern __shared__ char dyn[];
    __shared__ uint64_t mbar_store[NWARPS];
    __shared__ u64    s_iS2[3];     // {iSA, iSB}
    __shared__ u64    s_nc2[15];    // {-tA_ee*iSA, -tB_ee*iSB}
    __shared__ float  s_wsum[NWARPS];
    __shared__ bool   s_last;
    __shared__ double s_dsum[128];

    const int tid  = threadIdx.x;
    const int warp = tid >> 5;
    const int lane = tid & 31;
    const int grid = gridDim.x;
    const int bid  = blockIdx.x;

    if (tid < NWARPS)
        mbar_init((uint32_t)__cvta_generic_to_shared(&mbar_store[tid]), 1);
    if (tid == 0) {
        float mnA[3], mxA[3], mnB[3], mxB[3];
#pragma unroll
        for (int a = 0; a < 3; ++a) { mnA[a] = mxA[a] = tA[a]; mnB[a] = mxB[a] = tB[a]; }
#pragma unroll
        for (int j = 1; j < NJ; ++j) {
#pragma unroll
            for (int a = 0; a < 3; ++a) {
                const float va = tA[j * 3 + a];
                const float vb = tB[j * 3 + a];
                mnA[a] = fminf(mnA[a], va); mxA[a] = fmaxf(mxA[a], va);
                mnB[a] = fminf(mnB[a], vb); mxB[a] = fmaxf(mxB[a], vb);
            }
        }
        float iSA[3], iSB[3];
#pragma unroll
        for (int a = 0; a < 3; ++a) {
            iSA[a] = 1.0f / (mxA[a] - mnA[a]);
            iSB[a] = 1.0f / (mxB[a] - mnB[a]);
            s_iS2[a] = pk(iSA[a], iSB[a]);
        }
#pragma unroll
        for (int e = 0; e < 5; ++e) {
#pragma unroll
            for (int a = 0; a < 3; ++a) {
                s_nc2[e * 3 + a] = pk(-tA[END_SITES[e] * 3 + a] * iSA[a],
                                      -tB[END_SITES[e] * 3 + a] * iSB[a]);
            }
        }
    }
    __syncthreads();

    const int n_groups = grid * NWARPS;
    const int gidx     = bid * NWARPS + warp;
    const int S        = (F + FPS - 1) / FPS;                        // total slabs
    const int K        = (S > gidx) ? ((S - 1 - gidx) / n_groups + 1) : 0;

    char* const buf = dyn + warp * SLAB_BYTES;
    const uint32_t buf_u = (uint32_t)__cvta_generic_to_shared(buf);
    const uint32_t mb    = (uint32_t)__cvta_generic_to_shared(&mbar_store[warp]);

    const u64 C15  = pk(1.5f, 1.5f);
    const u64 CM05 = pk(-0.5f, -0.5f);
    const u64 CM1  = pk(-1.0f, -1.0f);

    float acc = 0.0f;
    uint32_t ph = 0;

    for (int i = 0; i < K; ++i) {
        const int s     = gidx + i * n_groups;
        int start       = s * FPS;
        if (start + FPS > F) start = F - FPS;       // clamp (F >= 32)
        const int fresh = s * FPS - start;          // lanes < fresh are repeats

        __syncwarp();                               // prior slab fully consumed
        if (lane == 0) {
            mbar_arrive_expect_tx(mb, SLAB_BYTES);
            bulk_g2s(buf_u,          poseA + (size_t)start * 144, PA_BYTES, mb);
            bulk_g2s(buf_u + OFF_PB, poseB + (size_t)start * 144, PA_BYTES, mb);
            bulk_g2s(buf_u + OFF_OA, offA  + (size_t)start * 72,  OA_BYTES, mb);
            bulk_g2s(buf_u + OFF_OB, offB  + (size_t)start * 72,  OA_BYTES, mb);
        }
        mbar_wait(mb, ph);
        ph ^= 1u;

        const float4* __restrict__ pra = (const float4*)(buf + lane * 576);
        const float4* __restrict__ prb = (const float4*)(buf + OFF_PB + lane * 576);
        const float4* __restrict__ ora = (const float4*)(buf + OFF_OA + lane * 288);
        const float4* __restrict__ orb = (const float4*)(buf + OFF_OB + lane * 288);

        // ---- packed FK: lo half = pose A, hi half = pose B ----
        u64 O[NJ][9];
        u64 P[NJ][3];
        float4 uA0, uA1, uA2, uB0, uB1, uB2;
#pragma unroll
        for (int j = 0; j < NJ; ++j) {
            if ((j & 3) == 0) {
                const int bb = (3 * j) / 4;
                uA0 = ora[bb]; uA1 = ora[bb + 1]; uA2 = ora[bb + 2];
                uB0 = orb[bb]; uB1 = orb[bb + 1]; uB2 = orb[bb + 2];
            }
            u64 ox, oy, oz;
            switch (j & 3) {
                case 0:  ox = pk(uA0.x, uB0.x); oy = pk(uA0.y, uB0.y); oz = pk(uA0.z, uB0.z); break;
                case 1:  ox = pk(uA0.w, uB0.w); oy = pk(uA1.x, uB1.x); oz = pk(uA1.y, uB1.y); break;
                case 2:  ox = pk(uA1.z, uB1.z); oy = pk(uA1.w, uB1.w); oz = pk(uA2.x, uB2.x); break;
                default: ox = pk(uA2.y, uB2.y); oy = pk(uA2.z, uB2.z); oz = pk(uA2.w, uB2.w); break;
            }

            u64 r0, r1, r2, r3, r4, r5, r6, r7, r8;
            if (!IS_EE[j]) {
                const int qi  = (6 * j) / 4;
                const int rem = (6 * j) % 4;        // 0 or 2
                const float4 xa = pra[qi], ya = pra[qi + 1];
                const float4 xb = prb[qi], yb = prb[qi + 1];
                u64 a0, a1, a2, a3, a4, a5;
                if (rem == 0) {
                    a0 = pk(xa.x, xb.x); a1 = pk(xa.y, xb.y); a2 = pk(xa.z, xb.z);
                    a3 = pk(xa.w, xb.w); a4 = pk(ya.x, yb.x); a5 = pk(ya.y, yb.y);
                } else {
                    a0 = pk(xa.z, xb.z); a1 = pk(xa.w, xb.w); a2 = pk(ya.x, yb.x);
                    a3 = pk(ya.y, yb.y); a4 = pk(ya.z, yb.z); a5 = pk(ya.w, yb.w);
                }

                u64 n1 = f2mul(a0, a0); n1 = f2fma(a1, a1, n1); n1 = f2fma(a2, a2, n1);
                const u64 i1 = rsq2(n1, C15, CM05);
                r0 = f2mul(a0, i1); r1 = f2mul(a1, i1); r2 = f2mul(a2, i1);
                u64 d = f2mul(r0, a3); d = f2fma(r1, a4, d); d = f2fma(r2, a5, d);
                const u64 nd = f2mul(d, CM1);
                const u64 c0 = f2fma(nd, r0, a3);
                const u64 c1 = f2fma(nd, r1, a4);
                const u64 c2 = f2fma(nd, r2, a5);
                u64 n2 = f2mul(c0, c0); n2 = f2fma(c1, c1, n2); n2 = f2fma(c2, c2, n2);
                const u64 i2 = rsq2(n2, C15, CM05);
                r3 = f2mul(c0, i2); r4 = f2mul(c1, i2); r5 = f2mul(c2, i2);
                const u64 m0 = f2mul(r0, CM1);
                const u64 m1 = f2mul(r1, CM1);
                const u64 m2 = f2mul(r2, CM1);
                r6 = f2fma(m2, r4, f2mul(r1, r5));
                r7 = f2fma(m0, r5, f2mul(r2, r3));
                r8 = f2fma(m1, r3, f2mul(r0, r4));
            }

            if (j == 0) {
                P[0][0] = ox; P[0][1] = oy; P[0][2] = oz;
                O[0][0] = r0; O[0][1] = r1; O[0][2] = r2;
                O[0][3] = r3; O[0][4] = r4; O[0][5] = r5;
                O[0][6] = r6; O[0][7] = r7; O[0][8] = r8;
            } else {
                const int p = PARENTS[j];
                u64 px = f2fma(O[p][0], ox, P[p][0]);
                px = f2fma(O[p][1], oy, px); px = f2fma(O[p][2], oz, px);
                u64 py = f2fma(O[p][3], ox, P[p][1]);
                py = f2fma(O[p][4], oy, py); py = f2fma(O[p][5], oz, py);
                u64 pz = f2fma(O[p][6], ox, P[p][2]);
                pz = f2fma(O[p][7], oy, pz); pz = f2fma(O[p][8], oz, pz);
                if (IS_EE[j]) {
                    const int sl = EE_SLOT[j];
                    const u64 v0 = f2fma(px, s_iS2[0], s_nc2[sl * 3 + 0]);
                    const u64 v1 = f2fma(py, s_iS2[1], s_nc2[sl * 3 + 1]);
                    const u64 v2 = f2fma(pz, s_iS2[2], s_nc2[sl * 3 + 2]);
                    float l0, h0, l1, h1, l2, h2;
                    upk(v0, l0, h0); upk(v1, l1, h1); upk(v2, l2, h2);
                    if (lane >= fresh) {
                        const float d0 = l0 - h0, d1 = l1 - h1, d2 = l2 - h2;
                        acc = fmaf(d0, d0, acc);
                        acc = fmaf(d1, d1, acc);
                        acc = fmaf(d2, d2, acc);
                    }
                } else {
                    P[j][0] = px; P[j][1] = py; P[j][2] = pz;
#pragma unroll
                    for (int c = 0; c < 3; ++c) {
#pragma unroll
                        for (int rr = 0; rr < 3; ++rr) {
                            u64 t = f2mul(O[p][rr * 3 + 0], (c == 0 ? r0 : (c == 1 ? r1 : r2)));
                            t = f2fma(O[p][rr * 3 + 1], (c == 0 ? r3 : (c == 1 ? r4 : r5)), t);
                            t = f2fma(O[p][rr * 3 + 2], (c == 0 ? r6 : (c == 1 ? r7 : r8)), t);
                            O[j][rr * 3 + c] = t;
                        }
                    }
                }
            }
        }
    }

    // ---- deterministic in-block reduction ----
#pragma unroll
    for (int o = 16; o > 0; o >>= 1)
        acc += __shfl_xor_sync(0xFFFFFFFFu, acc, o);
    if (lane == 0) s_wsum[warp] = acc;
    __syncthreads();

    if (tid == 0) {
        g_partials[bid] = s_wsum[0] + s_wsum[1] + s_wsum[2] + s_wsum[3];
        __threadfence();
        const unsigned int done = atomicAdd(&g_count, 1u);
        s_last = (done == (unsigned int)(grid - 1));
    }
    __syncthreads();

    if (s_last) {
        double ds = 0.0;
        for (int i = tid; i < grid; i += 128)
            ds += (double)g_partials[i];
        s_dsum[tid] = ds;
        __syncthreads();
#pragma unroll
        for (int k = 64; k > 0; k >>= 1) {
            if (tid < k) s_dsum[tid] += s_dsum[tid + k];
            __syncthreads();
        }
        if (tid == 0) {
            out[0] = (float)(s_dsum[0] * (double)inv_count);
            g_count = 0;   // reset for next graph replay
        }
    }
}

extern "C" void kernel_launch(void* const* d_in, const int* in_sizes, int n_in,
                              void* d_out, int out_size)
{
    const float* poseA = (const float*)d_in[0];
    const float* poseB = (const float*)d_in[1];
    const float* offA  = (const float*)d_in[2];
    const float* offB  = (const float*)d_in[3];
    const float* tA    = (const float*)d_in[4];
    const float* tB    = (const float*)d_in[5];
    float* out = (float*)d_out;

    const int F = in_sizes[0] / (NJ * 6);
    int dev = 0, sms = 148;
    cudaGetDevice(&dev);
    cudaDeviceGetAttribute(&sms, cudaDevAttrMultiProcessorCount, dev);
    if (sms > 16384) sms = 16384;

    cudaFuncSetAttribute(ee_loss_kernel,
                         cudaFuncAttributeMaxDynamicSharedMemorySize, DYN_SMEM);

    const float inv_count = 1.0f / ((float)F * 15.0f);
    ee_loss_kernel<<<sms, 128, DYN_SMEM>>>(poseA, poseB, offA, offB, tA, tB,
                                           out, F, inv_count);
}

// round 14
// speedup vs baseline: 1.3513x; 1.3513x over previous
#include <cuda_runtime.h>
#include <cstddef>

#define NJ 24

__device__ float g_partials[16384];
__device__ unsigned int g_count = 0;

// Fast inverse sqrt on the FMA pipe (avoids MUFU throughput bound).
__device__ __forceinline__ float rsq(float x) {
    float y = __int_as_float(0x5f3759dfu - (__float_as_uint(x) >> 1));
    float hx = 0.5f * x;
    y = y * (1.5f - hx * y * y);
    y = y * (1.5f - hx * y * y);
    return y;
}

// Forward kinematics for one frame of one pose; emits the 5 end-site positions.
// poseF: 144 floats (24 x 6), offF: 72 floats (24 x 3). Both 16B-aligned.
// Plain float4 loads (default caching): each 128B line is reused ~4.5x by the
// rolling q0/q1/q2 window out of L1 — do NOT use evict-first (.cs) here.
__device__ __forceinline__ void fk_ee(const float* __restrict__ poseF,
                                      const float* __restrict__ offF,
                                      float ee[5][3])
{
    constexpr int PARENTS[NJ] = {-1,0,0,0,1,2,3,4,5,6,7,8,9,9,9,12,13,14,16,17,18,19,20,21};
    constexpr bool IS_EE[NJ] = {false,false,false,false,false,false,false,false,false,false,
                                true, true, false,false,false,true, false,false,false,false,
                                false,false,true, true};
    constexpr int EE_SLOT[NJ] = {-1,-1,-1,-1,-1,-1,-1,-1,-1,-1,
                                  0, 1,-1,-1,-1, 2,-1,-1,-1,-1,
                                 -1,-1, 3, 4};

    float O[NJ][9];   // global orientations (row-major); scalarized by full unroll
    float P[NJ][3];   // global positions
    const float4* __restrict__ pv = reinterpret_cast<const float4*>(poseF);
    const float4* __restrict__ uv = reinterpret_cast<const float4*>(offF);
    float4 q0, q1, q2;   // rolling pose window (12 floats = 2 joints)
    float4 u0, u1, u2;   // rolling offset window (12 floats = 4 joints)

#pragma unroll
    for (int i = 0; i < NJ; ++i) {
        if ((i & 1) == 0) {
            const int b = (3 * i) / 2;          // float4 index of pose float 6*i
            q0 = pv[b]; q1 = pv[b + 1]; q2 = pv[b + 2];
        }
        float a0, a1, a2, a3, a4, a5;
        if ((i & 1) == 0) { a0 = q0.x; a1 = q0.y; a2 = q0.z; a3 = q0.w; a4 = q1.x; a5 = q1.y; }
        else              { a0 = q1.z; a1 = q1.w; a2 = q2.x; a3 = q2.y; a4 = q2.z; a5 = q2.w; }

        if ((i & 3) == 0) {
            const int b = (3 * i) / 4;          // float4 index of offset float 3*i
            u0 = uv[b]; u1 = uv[b + 1]; u2 = uv[b + 2];
        }
        float ox, oy, oz;
        switch (i & 3) {
            case 0:  ox = u0.x; oy = u0.y; oz = u0.z; break;
            case 1:  ox = u0.w; oy = u1.x; oz = u1.y; break;
            case 2:  ox = u1.z; oy = u1.w; oz = u2.x; break;
            default: ox = u2.y; oy = u2.z; oz = u2.w; break;
        }

        // 6D -> rotation matrix (rows b1,b2,b3). Skipped for leaf end-sites.
        float r0 = 0.f, r1 = 0.f, r2 = 0.f, r3 = 0.f, r4 = 0.f,
              r5 = 0.f, r6 = 0.f, r7 = 0.f, r8 = 0.f;
        if (!IS_EE[i]) {
            const float n1 = a0 * a0 + a1 * a1 + a2 * a2;
            const float i1 = rsq(n1);
            r0 = a0 * i1; r1 = a1 * i1; r2 = a2 * i1;
            const float d  = r0 * a3 + r1 * a4 + r2 * a5;
            const float c0 = a3 - d * r0;
            const float c1 = a4 - d * r1;
            const float c2 = a5 - d * r2;
            const float n2 = c0 * c0 + c1 * c1 + c2 * c2;
            const float i2 = rsq(n2);
            r3 = c0 * i2; r4 = c1 * i2; r5 = c2 * i2;
            r6 = r1 * r5 - r2 * r4;
            r7 = r2 * r3 - r0 * r5;
            r8 = r0 * r4 - r1 * r3;
        }

        if (i == 0) {
            P[0][0] = ox; P[0][1] = oy; P[0][2] = oz;
            O[0][0] = r0; O[0][1] = r1; O[0][2] = r2;
            O[0][3] = r3; O[0][4] = r4; O[0][5] = r5;
            O[0][6] = r6; O[0][7] = r7; O[0][8] = r8;
        } else {
            const int p = PARENTS[i];
            const float px = O[p][0] * ox + O[p][1] * oy + O[p][2] * oz + P[p][0];
            const float py = O[p][3] * ox + O[p][4] * oy + O[p][5] * oz + P[p][1];
            const float pz = O[p][6] * ox + O[p][7] * oy + O[p][8] * oz + P[p][2];
            if (IS_EE[i]) {
                const int s = EE_SLOT[i];
                ee[s][0] = px; ee[s][1] = py; ee[s][2] = pz;
            } else {
                P[i][0] = px; P[i][1] = py; P[i][2] = pz;
                // O[i] = O[p] @ R
                O[i][0] = O[p][0] * r0 + O[p][1] * r3 + O[p][2] * r6;
                O[i][1] = O[p][0] * r1 + O[p][1] * r4 + O[p][2] * r7;
                O[i][2] = O[p][0] * r2 + O[p][1] * r5 + O[p][2] * r8;
                O[i][3] = O[p][3] * r0 + O[p][4] * r3 + O[p][5] * r6;
                O[i][4] = O[p][3] * r1 + O[p][4] * r4 + O[p][5] * r7;
                O[i][5] = O[p][3] * r2 + O[p][4] * r5 + O[p][5] * r8;
                O[i][6] = O[p][6] * r0 + O[p][7] * r3 + O[p][8] * r6;
                O[i][7] = O[p][6] * r1 + O[p][7] * r4 + O[p][8] * r7;
                O[i][8] = O[p][6] * r2 + O[p][7] * r5 + O[p][8] * r8;
            }
        }
    }
}

__global__ void __launch_bounds__(64)
ee_loss_kernel(const float* __restrict__ poseA, const float* __restrict__ poseB,
               const float* __restrict__ offA,  const float* __restrict__ offB,
               const float* __restrict__ tA,    const float* __restrict__ tB,
               float* __restrict__ out,
               int F, int nb, float inv_count)
{
    constexpr int END_SITES[5] = {10,11,15,22,23};
    __shared__ float s_iSA[3], s_iSB[3], s_c[15];   // c = tEA*iSA - tEB*iSB
    __shared__ float s_wsum[2];
    __shared__ bool  s_last;
    __shared__ double s_dsum[64];

    if (threadIdx.x == 0) {
        float mnA[3], mxA[3], mnB[3], mxB[3];
#pragma unroll
        for (int a = 0; a < 3; ++a) {
            mnA[a] = mxA[a] = tA[a];
            mnB[a] = mxB[a] = tB[a];
        }
#pragma unroll
        for (int j = 1; j < NJ; ++j) {
#pragma unroll
            for (int a = 0; a < 3; ++a) {
                const float va = tA[j * 3 + a];
                const float vb = tB[j * 3 + a];
                mnA[a] = fminf(mnA[a], va); mxA[a] = fmaxf(mxA[a], va);
                mnB[a] = fminf(mnB[a], vb); mxB[a] = fmaxf(mxB[a], vb);
            }
        }
        float iSA[3], iSB[3];
#pragma unroll
        for (int a = 0; a < 3; ++a) {
            iSA[a] = 1.0f / (mxA[a] - mnA[a]);
            iSB[a] = 1.0f / (mxB[a] - mnB[a]);
            s_iSA[a] = iSA[a];
            s_iSB[a] = iSB[a];
        }
#pragma unroll
        for (int e = 0; e < 5; ++e) {
#pragma unroll
            for (int a = 0; a < 3; ++a) {
                s_c[e * 3 + a] = tA[END_SITES[e] * 3 + a] * iSA[a]
                               - tB[END_SITES[e] * 3 + a] * iSB[a];
            }
        }
    }
    __syncthreads();

    const int frame = blockIdx.x * blockDim.x + threadIdx.x;
    float s = 0.0f;
    if (frame < F) {
        float eeA[5][3], eeB[5][3];
        fk_ee(poseA + (size_t)frame * 144, offA + (size_t)frame * 72, eeA);
        fk_ee(poseB + (size_t)frame * 144, offB + (size_t)frame * 72, eeB);
#pragma unroll
        for (int e = 0; e < 5; ++e) {
#pragma unroll
            for (int a = 0; a < 3; ++a) {
                const float d = eeA[e][a] * s_iSA[a]
                              - eeB[e][a] * s_iSB[a]
                              - s_c[e * 3 + a];
                s = fmaf(d, d, s);
            }
        }
    }

    // deterministic in-block reduction
#pragma unroll
    for (int o = 16; o > 0; o >>= 1)
        s += __shfl_xor_sync(0xFFFFFFFFu, s, o);
    const int wid  = threadIdx.x >> 5;
    const int lane = threadIdx.x & 31;
    if (lane == 0) s_wsum[wid] = s;
    __syncthreads();

    if (threadIdx.x == 0) {
        g_partials[blockIdx.x] = s_wsum[0] + s_wsum[1];
        __threadfence();
        const unsigned int done = atomicAdd(&g_count, 1u);
        s_last = (done == (unsigned int)(nb - 1));
    }
    __syncthreads();

    // Last block to finish reduces all partials in a FIXED order
    // (independent of which block it is) -> deterministic; writes d_out
    // directly so the graph has a single kernel node.
    if (s_last) {
        double ds = 0.0;
        for (int i = threadIdx.x; i < nb; i += 64)
            ds += (double)g_partials[i];
        s_dsum[threadIdx.x] = ds;
        __syncthreads();
#pragma unroll
        for (int k = 32; k > 0; k >>= 1) {
            if (threadIdx.x < k) s_dsum[threadIdx.x] += s_dsum[threadIdx.x + k];
            __syncthreads();
        }
        if (threadIdx.x == 0) {
            out[0] = (float)(s_dsum[0] * (double)inv_count);
            g_count = 0;   // reset for the next graph replay
        }
    }
}

extern "C" void kernel_launch(void* const* d_in, const int* in_sizes, int n_in,
                              void* d_out, int out_size)
{
    const float* poseA = (const float*)d_in[0];
    const float* poseB = (const float*)d_in[1];
    const float* offA  = (const float*)d_in[2];
    const float* offB  = (const float*)d_in[3];
    const float* tA    = (const float*)d_in[4];
    const float* tB    = (const float*)d_in[5];
    float* out = (float*)d_out;

    const int F = in_sizes[0] / (NJ * 6);
    const int threads = 64;
    const int nb = (F + threads - 1) / threads;
    const float inv_count = 1.0f / ((float)F * 15.0f);

    ee_loss_kernel<<<nb, threads>>>(poseA, poseB, offA, offB, tA, tB, out, F, nb, inv_count);
}